// round 1
// baseline (speedup 1.0000x reference)
#include <cuda_runtime.h>
#include <math.h>

// Problem constants
#define BSZ 2
#define HN  16
#define SQ  2048
#define DH  64
#define EMB 1024
#define BH  (BSZ*HN)

// Scratch (device globals; no allocations allowed)
__device__ float g_Qh[(size_t)BH * SQ * DH];      // [B,H,S,D]
__device__ float g_Kh[(size_t)BH * SQ * DH];
__device__ float g_Vh[(size_t)BH * SQ * DH];
__device__ float g_ctx[(size_t)BSZ * SQ * EMB];   // [B,S,E]
__device__ float g_attn_fb[(size_t)BH * SQ * SQ]; // fallback if attn not in d_out

// ---------------------------------------------------------------------------
// Generic TN GEMM: C[m,n] = sum_k A[m,k]*W[n,k] + bias[n]
// BM=BN=128, BK=16, 256 threads, 8x8 per thread.
// MODE 0: A := g_ctx, store C[m*N+n]                  (output projection)
// MODE 1/2/3: A := arg, scatter-store to g_Qh/g_Kh/g_Vh in [B,H,S,D] layout
// ---------------------------------------------------------------------------
template<int MODE>
__global__ void __launch_bounds__(256) gemm_tn(const float* __restrict__ A,
                                               const float* __restrict__ W,
                                               const float* __restrict__ bias,
                                               float* __restrict__ C,
                                               int M, int N, int K)
{
    __shared__ float As[16][128];
    __shared__ float Bs[16][128];
    const float* Ap = (MODE == 0) ? g_ctx : A;

    int tid = threadIdx.x;
    int tx = tid & 15, ty = tid >> 4;
    int m0 = blockIdx.y * 128, n0 = blockIdx.x * 128;
    int lr = tid >> 2, lc = (tid & 3) << 2;

    float acc[8][8];
#pragma unroll
    for (int i = 0; i < 8; i++)
#pragma unroll
        for (int j = 0; j < 8; j++) acc[i][j] = 0.f;

    for (int k0 = 0; k0 < K; k0 += 16) {
#pragma unroll
        for (int i = 0; i < 2; i++) {
            int row = lr + i * 64;
            float4 v = *(const float4*)(Ap + (size_t)(m0 + row) * K + k0 + lc);
            As[lc][row] = v.x; As[lc+1][row] = v.y; As[lc+2][row] = v.z; As[lc+3][row] = v.w;
            float4 w = *(const float4*)(W + (size_t)(n0 + row) * K + k0 + lc);
            Bs[lc][row] = w.x; Bs[lc+1][row] = w.y; Bs[lc+2][row] = w.z; Bs[lc+3][row] = w.w;
        }
        __syncthreads();
#pragma unroll
        for (int k = 0; k < 16; k++) {
            float a[8], b[8];
#pragma unroll
            for (int i = 0; i < 8; i++) a[i] = As[k][ty * 8 + i];
#pragma unroll
            for (int j = 0; j < 8; j++) b[j] = Bs[k][tx * 8 + j];
#pragma unroll
            for (int i = 0; i < 8; i++)
#pragma unroll
                for (int j = 0; j < 8; j++)
                    acc[i][j] = fmaf(a[i], b[j], acc[i][j]);
        }
        __syncthreads();
    }

#pragma unroll
    for (int i = 0; i < 8; i++) {
        int m = m0 + ty * 8 + i;
#pragma unroll
        for (int j = 0; j < 8; j++) {
            int n = n0 + tx * 8 + j;
            float v = acc[i][j] + bias[n];
            if (MODE == 0) {
                C[(size_t)m * N + n] = v;
            } else {
                int b = m / SQ, s = m % SQ;
                int h = n / DH, d = n % DH;
                float* dst = (MODE == 1) ? g_Qh : (MODE == 2 ? g_Kh : g_Vh);
                dst[((size_t)(b * HN + h) * SQ + s) * DH + d] = v;
            }
        }
    }
}

// ---------------------------------------------------------------------------
// Causal scores: attn[bh,q,k] = 0.125 * dot(Q[bh,q,:], K[bh,k,:]) for k<=q, else 0
// Tiles strictly above the diagonal are zero-filled without compute.
// ---------------------------------------------------------------------------
__global__ void __launch_bounds__(256) scores_kernel(float* __restrict__ attn)
{
    int bh = blockIdx.z;
    int bm = blockIdx.y, bn = blockIdx.x;
    float* out = attn + (size_t)bh * SQ * SQ;
    int tid = threadIdx.x;

    if (bn > bm) { // fully masked tile -> final value 0
#pragma unroll
        for (int it = 0; it < 16; it++) {
            int idx = it * 256 + tid;       // 4096 float4s = 128x128
            int r = idx >> 5;
            int c = idx & 31;
            *(float4*)(out + (size_t)(bm * 128 + r) * SQ + bn * 128 + c * 4) =
                make_float4(0.f, 0.f, 0.f, 0.f);
        }
        return;
    }

    const float* Q  = g_Qh + (size_t)bh * SQ * DH;
    const float* Kp = g_Kh + (size_t)bh * SQ * DH;

    __shared__ float As[16][128];
    __shared__ float Bs[16][128];
    int tx = tid & 15, ty = tid >> 4;
    int lr = tid >> 2, lc = (tid & 3) << 2;

    float acc[8][8];
#pragma unroll
    for (int i = 0; i < 8; i++)
#pragma unroll
        for (int j = 0; j < 8; j++) acc[i][j] = 0.f;

    for (int k0 = 0; k0 < DH; k0 += 16) {
#pragma unroll
        for (int i = 0; i < 2; i++) {
            int row = lr + i * 64;
            float4 v = *(const float4*)(Q  + (size_t)(bm * 128 + row) * DH + k0 + lc);
            As[lc][row] = v.x; As[lc+1][row] = v.y; As[lc+2][row] = v.z; As[lc+3][row] = v.w;
            float4 w = *(const float4*)(Kp + (size_t)(bn * 128 + row) * DH + k0 + lc);
            Bs[lc][row] = w.x; Bs[lc+1][row] = w.y; Bs[lc+2][row] = w.z; Bs[lc+3][row] = w.w;
        }
        __syncthreads();
#pragma unroll
        for (int k = 0; k < 16; k++) {
            float a[8], b[8];
#pragma unroll
            for (int i = 0; i < 8; i++) a[i] = As[k][ty * 8 + i];
#pragma unroll
            for (int j = 0; j < 8; j++) b[j] = Bs[k][tx * 8 + j];
#pragma unroll
            for (int i = 0; i < 8; i++)
#pragma unroll
                for (int j = 0; j < 8; j++)
                    acc[i][j] = fmaf(a[i], b[j], acc[i][j]);
        }
        __syncthreads();
    }

    const float scale = 0.125f; // 1/sqrt(64)
#pragma unroll
    for (int i = 0; i < 8; i++) {
        int r = bm * 128 + ty * 8 + i;
#pragma unroll
        for (int j = 0; j < 8; j++) {
            int c = bn * 128 + tx * 8 + j;
            out[(size_t)r * SQ + c] = (c <= r) ? acc[i][j] * scale : 0.f;
        }
    }
}

// ---------------------------------------------------------------------------
// In-place causal row softmax. One 256-thread block per row; row q has q+1
// live entries (the rest are already exact zeros).
// ---------------------------------------------------------------------------
__global__ void __launch_bounds__(256) softmax_kernel(float* __restrict__ attn)
{
    size_t rid = blockIdx.x;
    int q = (int)(rid & (SQ - 1));
    float* row = attn + rid * SQ;
    int L = q + 1;
    int tid = threadIdx.x;
    __shared__ float sred[8];

    float m = -INFINITY;
    for (int j = tid; j < L; j += 256) m = fmaxf(m, row[j]);
#pragma unroll
    for (int o = 16; o; o >>= 1) m = fmaxf(m, __shfl_xor_sync(0xffffffffu, m, o));
    if ((tid & 31) == 0) sred[tid >> 5] = m;
    __syncthreads();
    if (tid < 32) {
        float x = (tid < 8) ? sred[tid] : -INFINITY;
#pragma unroll
        for (int o = 4; o; o >>= 1) x = fmaxf(x, __shfl_xor_sync(0xffffffffu, x, o));
        if (tid == 0) sred[0] = x;
    }
    __syncthreads();
    m = sred[0];
    __syncthreads();

    float s = 0.f;
    for (int j = tid; j < L; j += 256) {
        float e = __expf(row[j] - m);
        row[j] = e;
        s += e;
    }
#pragma unroll
    for (int o = 16; o; o >>= 1) s += __shfl_xor_sync(0xffffffffu, s, o);
    if ((tid & 31) == 0) sred[tid >> 5] = s;
    __syncthreads();
    if (tid < 32) {
        float x = (tid < 8) ? sred[tid] : 0.f;
#pragma unroll
        for (int o = 4; o; o >>= 1) x += __shfl_xor_sync(0xffffffffu, x, o);
        if (tid == 0) sred[0] = x;
    }
    __syncthreads();
    float inv = 1.f / sred[0];
    for (int j = tid; j < L; j += 256) row[j] *= inv;
}

// ---------------------------------------------------------------------------
// PV: ctx[b,s,h*64+d] = sum_k attn[bh,q,k] * V[bh,k,d]; causal -> K loop
// truncated at the row block's diagonal. BM=128, BN=64, BK=16.
// ---------------------------------------------------------------------------
__global__ void __launch_bounds__(256) pv_kernel(const float* __restrict__ attn)
{
    int bh = blockIdx.z;
    int b = bh >> 4, h = bh & 15;
    int bm = blockIdx.y;
    const float* Ar = attn + (size_t)bh * SQ * SQ;
    const float* V  = g_Vh + (size_t)bh * SQ * DH;

    __shared__ float As[16][128];
    __shared__ float Bs[16][64];
    int tid = threadIdx.x;
    int tx = tid & 15, ty = tid >> 4;
    int lrA = tid >> 2, lcA = (tid & 3) << 2;
    int lrB = tid >> 4, lcB = (tid & 15) << 2;

    float acc[8][4];
#pragma unroll
    for (int i = 0; i < 8; i++)
#pragma unroll
        for (int j = 0; j < 4; j++) acc[i][j] = 0.f;

    int kmax = (bm + 1) * 128;  // causal truncation
    for (int k0 = 0; k0 < kmax; k0 += 16) {
#pragma unroll
        for (int i = 0; i < 2; i++) {
            int row = lrA + i * 64;
            float4 v = *(const float4*)(Ar + (size_t)(bm * 128 + row) * SQ + k0 + lcA);
            As[lcA][row] = v.x; As[lcA+1][row] = v.y; As[lcA+2][row] = v.z; As[lcA+3][row] = v.w;
        }
        *(float4*)&Bs[lrB][lcB] = *(const float4*)(V + (size_t)(k0 + lrB) * DH + lcB);
        __syncthreads();
#pragma unroll
        for (int k = 0; k < 16; k++) {
            float a[8], bb[4];
#pragma unroll
            for (int i = 0; i < 8; i++) a[i] = As[k][ty * 8 + i];
#pragma unroll
            for (int j = 0; j < 4; j++) bb[j] = Bs[k][tx * 4 + j];
#pragma unroll
            for (int i = 0; i < 8; i++)
#pragma unroll
                for (int j = 0; j < 4; j++)
                    acc[i][j] = fmaf(a[i], bb[j], acc[i][j]);
        }
        __syncthreads();
    }

#pragma unroll
    for (int i = 0; i < 8; i++) {
        int qrow = bm * 128 + ty * 8 + i;
        float4 v = make_float4(acc[i][0], acc[i][1], acc[i][2], acc[i][3]);
        *(float4*)(g_ctx + ((size_t)(b * SQ + qrow)) * EMB + h * DH + tx * 4) = v;
    }
}

// ---------------------------------------------------------------------------
extern "C" void kernel_launch(void* const* d_in, const int* in_sizes, int n_in,
                              void* d_out, int out_size)
{
    const float* query = (const float*)d_in[0];
    const float* key_  = (const float*)d_in[1];
    const float* value = (const float*)d_in[2];
    const float* Wq = (const float*)d_in[3];
    const float* bq = (const float*)d_in[4];
    const float* Wk = (const float*)d_in[5];
    const float* bk = (const float*)d_in[6];
    const float* Wv = (const float*)d_in[7];
    const float* bv = (const float*)d_in[8];
    const float* Wo = (const float*)d_in[9];
    const float* bo = (const float*)d_in[10];

    const long long OUT_E = (long long)BSZ * SQ * EMB;  // 4,194,304
    const long long ATT_E = (long long)BH * SQ * SQ;    // 134,217,728

    float* outp = (float*)d_out;
    float* attn;
    if ((long long)out_size >= OUT_E + ATT_E) {
        attn = outp + OUT_E;  // tuple output: (out, attn) concatenated
    } else {
        void* p = nullptr;
        cudaGetSymbolAddress(&p, g_attn_fb);
        attn = (float*)p;
    }

    const int M = BSZ * SQ;   // 4096

    dim3 gproj(EMB / 128, M / 128);       // (8, 32)
    gemm_tn<1><<<gproj, 256>>>(query, Wq, bq, nullptr, M, EMB, EMB);
    gemm_tn<2><<<gproj, 256>>>(key_,  Wk, bk, nullptr, M, EMB, EMB);
    gemm_tn<3><<<gproj, 256>>>(value, Wv, bv, nullptr, M, EMB, EMB);

    dim3 gsc(SQ / 128, SQ / 128, BH);     // (16, 16, 32)
    scores_kernel<<<gsc, 256>>>(attn);

    softmax_kernel<<<BH * SQ, 256>>>(attn);

    dim3 gpv(1, SQ / 128, BH);            // (1, 16, 32)
    pv_kernel<<<gpv, 256>>>(attn);

    dim3 gout(EMB / 128, M / 128);        // (8, 32)
    gemm_tn<0><<<gout, 256>>>(nullptr, Wo, bo, outp, M, EMB, EMB);
}

// round 3
// speedup vs baseline: 2.3101x; 2.3101x over previous
#include <cuda_runtime.h>
#include <math.h>
#include <stdint.h>

// Problem constants
#define BSZ 2
#define HN  16
#define SQ  2048
#define DH  64
#define EMB 1024
#define BH  (BSZ*HN)

// Scratch (device globals; no allocations allowed)
__device__ float g_Qh[(size_t)BH * SQ * DH];      // [B,H,S,D]
__device__ float g_Kh[(size_t)BH * SQ * DH];
__device__ float g_Vh[(size_t)BH * SQ * DH];
__device__ float g_ctx[(size_t)BSZ * SQ * EMB];   // [B,S,E]
__device__ float g_attn_fb[(size_t)BH * SQ * SQ]; // fallback if attn not in d_out

// ===========================================================================
// mma.sync tf32 helpers (sm_80+ baseline PTX; no 'a'-gated features)
// ===========================================================================
__device__ __forceinline__ uint32_t f2tf(float x) {
    uint32_t r;
    asm("cvt.rna.tf32.f32 %0, %1;" : "=r"(r) : "f"(x));
    return r;
}

// D = A(16x8 tf32 row) * B(8x8 tf32 col) + D, fp32 accum
#define MMA_TF32(c, A0, A1, A2, A3, B0, B1)                                      \
    asm volatile("mma.sync.aligned.m16n8k8.row.col.f32.tf32.tf32.f32 "           \
                 "{%0,%1,%2,%3},{%4,%5,%6,%7},{%8,%9},{%0,%1,%2,%3};"            \
                 : "+f"((c)[0]), "+f"((c)[1]), "+f"((c)[2]), "+f"((c)[3])        \
                 : "r"(A0), "r"(A1), "r"(A2), "r"(A3), "r"(B0), "r"(B1))

// ===========================================================================
// TN GEMM via mma.sync tf32: C[m,n] = sum_k A[m,k]*W[n,k] + bias[n]
// 128x128 tile, BK=32, 256 threads (8 warps, each 32m x 64n).
// MODE 0: A := g_ctx, C[m*EMB+n]. MODE 1/2/3: scatter to g_Qh/g_Kh/g_Vh.
// ===========================================================================
template<int MODE>
__global__ void __launch_bounds__(256, 2) gemm_mma(const float* __restrict__ A,
                                                   const float* __restrict__ W,
                                                   const float* __restrict__ bias,
                                                   float* __restrict__ C)
{
    constexpr int K = EMB;        // 1024
    constexpr int LD = 36;        // row stride (floats): stride%32==4 -> conflict-free frags

    __shared__ uint32_t As[128 * LD];
    __shared__ uint32_t Bs[128 * LD];

    const int tid  = threadIdx.x;
    const int wid  = tid >> 5, lane = tid & 31;
    const int g    = lane >> 2, t = lane & 3;
    const int wm   = (wid & 3) * 32;     // warp m offset in tile
    const int wn   = (wid >> 2) * 64;    // warp n offset in tile
    const int m0   = blockIdx.y * 128, n0 = blockIdx.x * 128;

    const float* __restrict__ Ap = (MODE == 0) ? g_ctx : A;

    // Loader mapping: row = (tid>>3)+32i (i=0..3), kquad c4 = tid&7
    const int lrow = tid >> 3;
    const int lc4  = tid & 7;
    const float* pA = Ap + (size_t)(m0 + lrow) * K + lc4 * 4;
    const float* pB = W  + (size_t)(n0 + lrow) * K + lc4 * 4;

    float acc[2][8][4];
#pragma unroll
    for (int i = 0; i < 2; i++)
#pragma unroll
        for (int j = 0; j < 8; j++)
#pragma unroll
            for (int l = 0; l < 4; l++) acc[i][j][l] = 0.f;

    float4 ra[4], rb[4];
#pragma unroll
    for (int i = 0; i < 4; i++) {
        ra[i] = *(const float4*)(pA + (size_t)(32 * i) * K);
        rb[i] = *(const float4*)(pB + (size_t)(32 * i) * K);
    }

    for (int kb = 0; kb < K / 32; kb++) {
        // store staged regs (tf32-converted) to smem
#pragma unroll
        for (int i = 0; i < 4; i++) {
            uint32_t* da = &As[(lrow + 32 * i) * LD + lc4 * 4];
            da[0] = f2tf(ra[i].x); da[1] = f2tf(ra[i].y);
            da[2] = f2tf(ra[i].z); da[3] = f2tf(ra[i].w);
            uint32_t* db = &Bs[(lrow + 32 * i) * LD + lc4 * 4];
            db[0] = f2tf(rb[i].x); db[1] = f2tf(rb[i].y);
            db[2] = f2tf(rb[i].z); db[3] = f2tf(rb[i].w);
        }
        __syncthreads();

        // prefetch next k-block while computing this one
        if (kb + 1 < K / 32) {
#pragma unroll
            for (int i = 0; i < 4; i++) {
                ra[i] = *(const float4*)(pA + (size_t)(32 * i) * K + (kb + 1) * 32);
                rb[i] = *(const float4*)(pB + (size_t)(32 * i) * K + (kb + 1) * 32);
            }
        }

#pragma unroll
        for (int kt = 0; kt < 4; kt++) {
            const int k = kt * 8;
            uint32_t af[2][4];
#pragma unroll
            for (int mt = 0; mt < 2; mt++) {
                const int r = wm + mt * 16 + g;
                af[mt][0] = As[r * LD + k + t];
                af[mt][1] = As[(r + 8) * LD + k + t];
                af[mt][2] = As[r * LD + k + t + 4];
                af[mt][3] = As[(r + 8) * LD + k + t + 4];
            }
#pragma unroll
            for (int nt = 0; nt < 8; nt++) {
                const int n = wn + nt * 8 + g;
                const uint32_t b0 = Bs[n * LD + k + t];
                const uint32_t b1 = Bs[n * LD + k + t + 4];
#pragma unroll
                for (int mt = 0; mt < 2; mt++)
                    MMA_TF32(acc[mt][nt], af[mt][0], af[mt][1], af[mt][2], af[mt][3], b0, b1);
            }
        }
        __syncthreads();
    }

    // Epilogue: c0:(g,2t) c1:(g,2t+1) c2:(g+8,2t) c3:(g+8,2t+1)
#pragma unroll
    for (int nt = 0; nt < 8; nt++) {
        const int n = n0 + wn + nt * 8 + 2 * t;
        const float b0 = bias[n], b1 = bias[n + 1];
#pragma unroll
        for (int mt = 0; mt < 2; mt++) {
            const int mlo = m0 + wm + mt * 16 + g;
            const int mhi = mlo + 8;
            float2 vlo = make_float2(acc[mt][nt][0] + b0, acc[mt][nt][1] + b1);
            float2 vhi = make_float2(acc[mt][nt][2] + b0, acc[mt][nt][3] + b1);
            if (MODE == 0) {
                *(float2*)(C + (size_t)mlo * EMB + n) = vlo;
                *(float2*)(C + (size_t)mhi * EMB + n) = vhi;
            } else {
                const int h = n >> 6, dd = n & 63;
                float* dst = (MODE == 1) ? g_Qh : (MODE == 2 ? g_Kh : g_Vh);
                const int blo = mlo / SQ, slo = mlo % SQ;
                const int bhi = mhi / SQ, shi = mhi % SQ;
                *(float2*)(dst + ((size_t)(blo * HN + h) * SQ + slo) * DH + dd) = vlo;
                *(float2*)(dst + ((size_t)(bhi * HN + h) * SQ + shi) * DH + dd) = vhi;
            }
        }
    }
}

// ---------------------------------------------------------------------------
// Causal scores via mma.sync tf32: attn[bh,q,k] = 0.125*dot(Q[q],K[k]), k<=q
// 128x128 tile per CTA, K=64 single stage. Above-diagonal tiles: zero-fill.
// ---------------------------------------------------------------------------
#define SC_LD 68  // 64 + 4 pad: stride%32==4 -> conflict-free fragment LDS
#define SC_SMEM (2 * 128 * SC_LD * 4)

__global__ void __launch_bounds__(256) scores_mma(float* __restrict__ attn)
{
    const int bh = blockIdx.z;
    const int bm = blockIdx.y, bn = blockIdx.x;
    float* out = attn + (size_t)bh * SQ * SQ;
    const int tid = threadIdx.x;

    if (bn > bm) { // fully masked tile -> exact zeros
#pragma unroll
        for (int it = 0; it < 16; it++) {
            int idx = it * 256 + tid;
            int r = idx >> 5;
            int c = idx & 31;
            *(float4*)(out + (size_t)(bm * 128 + r) * SQ + bn * 128 + c * 4) =
                make_float4(0.f, 0.f, 0.f, 0.f);
        }
        return;
    }

    extern __shared__ uint32_t sc_smem[];
    uint32_t* Qs = sc_smem;                  // [128][68]
    uint32_t* Ks = sc_smem + 128 * SC_LD;    // [128][68]

    const float* Q  = g_Qh + (size_t)bh * SQ * DH;
    const float* Kp = g_Kh + (size_t)bh * SQ * DH;

    // load tiles: row = (tid>>4)+16i, quad q4 = tid&15
    const int lrow = tid >> 4;
    const int lq4  = tid & 15;
#pragma unroll
    for (int i = 0; i < 8; i++) {
        const int r = lrow + 16 * i;
        float4 vq = *(const float4*)(Q  + (size_t)(bm * 128 + r) * DH + lq4 * 4);
        float4 vk = *(const float4*)(Kp + (size_t)(bn * 128 + r) * DH + lq4 * 4);
        uint32_t* dq = &Qs[r * SC_LD + lq4 * 4];
        dq[0] = f2tf(vq.x); dq[1] = f2tf(vq.y); dq[2] = f2tf(vq.z); dq[3] = f2tf(vq.w);
        uint32_t* dk = &Ks[r * SC_LD + lq4 * 4];
        dk[0] = f2tf(vk.x); dk[1] = f2tf(vk.y); dk[2] = f2tf(vk.z); dk[3] = f2tf(vk.w);
    }
    __syncthreads();

    const int wid = tid >> 5, lane = tid & 31;
    const int g = lane >> 2, t = lane & 3;
    const int wm = (wid & 3) * 32;
    const int wn = (wid >> 2) * 64;

    float acc[2][8][4];
#pragma unroll
    for (int i = 0; i < 2; i++)
#pragma unroll
        for (int j = 0; j < 8; j++)
#pragma unroll
            for (int l = 0; l < 4; l++) acc[i][j][l] = 0.f;

#pragma unroll
    for (int kt = 0; kt < 8; kt++) {
        const int k = kt * 8;
        uint32_t af[2][4];
#pragma unroll
        for (int mt = 0; mt < 2; mt++) {
            const int r = wm + mt * 16 + g;
            af[mt][0] = Qs[r * SC_LD + k + t];
            af[mt][1] = Qs[(r + 8) * SC_LD + k + t];
            af[mt][2] = Qs[r * SC_LD + k + t + 4];
            af[mt][3] = Qs[(r + 8) * SC_LD + k + t + 4];
        }
#pragma unroll
        for (int nt = 0; nt < 8; nt++) {
            const int n = wn + nt * 8 + g;
            const uint32_t b0 = Ks[n * SC_LD + k + t];
            const uint32_t b1 = Ks[n * SC_LD + k + t + 4];
#pragma unroll
            for (int mt = 0; mt < 2; mt++)
                MMA_TF32(acc[mt][nt], af[mt][0], af[mt][1], af[mt][2], af[mt][3], b0, b1);
        }
    }

    const float scale = 0.125f; // 1/sqrt(64)
#pragma unroll
    for (int nt = 0; nt < 8; nt++) {
        const int c = bn * 128 + wn + nt * 8 + 2 * t;
#pragma unroll
        for (int mt = 0; mt < 2; mt++) {
            const int rlo = bm * 128 + wm + mt * 16 + g;
            const int rhi = rlo + 8;
            float2 vlo = make_float2(c <= rlo ? acc[mt][nt][0] * scale : 0.f,
                                     c + 1 <= rlo ? acc[mt][nt][1] * scale : 0.f);
            float2 vhi = make_float2(c <= rhi ? acc[mt][nt][2] * scale : 0.f,
                                     c + 1 <= rhi ? acc[mt][nt][3] * scale : 0.f);
            *(float2*)(out + (size_t)rlo * SQ + c) = vlo;
            *(float2*)(out + (size_t)rhi * SQ + c) = vhi;
        }
    }
}

// ---------------------------------------------------------------------------
// In-place causal row softmax.
// ---------------------------------------------------------------------------
__global__ void __launch_bounds__(256) softmax_kernel(float* __restrict__ attn)
{
    size_t rid = blockIdx.x;
    int q = (int)(rid & (SQ - 1));
    float* row = attn + rid * SQ;
    int L = q + 1;
    int tid = threadIdx.x;
    __shared__ float sred[8];

    float m = -INFINITY;
    for (int j = tid; j < L; j += 256) m = fmaxf(m, row[j]);
#pragma unroll
    for (int o = 16; o; o >>= 1) m = fmaxf(m, __shfl_xor_sync(0xffffffffu, m, o));
    if ((tid & 31) == 0) sred[tid >> 5] = m;
    __syncthreads();
    if (tid < 32) {
        float x = (tid < 8) ? sred[tid] : -INFINITY;
#pragma unroll
        for (int o = 4; o; o >>= 1) x = fmaxf(x, __shfl_xor_sync(0xffffffffu, x, o));
        if (tid == 0) sred[0] = x;
    }
    __syncthreads();
    m = sred[0];
    __syncthreads();

    float s = 0.f;
    for (int j = tid; j < L; j += 256) {
        float e = __expf(row[j] - m);
        row[j] = e;
        s += e;
    }
#pragma unroll
    for (int o = 16; o; o >>= 1) s += __shfl_xor_sync(0xffffffffu, s, o);
    if ((tid & 31) == 0) sred[tid >> 5] = s;
    __syncthreads();
    if (tid < 32) {
        float x = (tid < 8) ? sred[tid] : 0.f;
#pragma unroll
        for (int o = 4; o; o >>= 1) x += __shfl_xor_sync(0xffffffffu, x, o);
        if (tid == 0) sred[0] = x;
    }
    __syncthreads();
    float inv = 1.f / sred[0];
    for (int j = tid; j < L; j += 256) row[j] *= inv;
}

// ---------------------------------------------------------------------------
// PV: ctx[b,s,h*64+d] = sum_k attn[bh,q,k] * V[bh,k,d]; causal truncation.
// ---------------------------------------------------------------------------
__global__ void __launch_bounds__(256) pv_kernel(const float* __restrict__ attn)
{
    int bh = blockIdx.z;
    int b = bh >> 4, h = bh & 15;
    int bm = blockIdx.y;
    const float* Ar = attn + (size_t)bh * SQ * SQ;
    const float* V  = g_Vh + (size_t)bh * SQ * DH;

    __shared__ float As[16][128];
    __shared__ float Bs[16][64];
    int tid = threadIdx.x;
    int tx = tid & 15, ty = tid >> 4;
    int lrA = tid >> 2, lcA = (tid & 3) << 2;
    int lrB = tid >> 4, lcB = (tid & 15) << 2;

    float acc[8][4];
#pragma unroll
    for (int i = 0; i < 8; i++)
#pragma unroll
        for (int j = 0; j < 4; j++) acc[i][j] = 0.f;

    int kmax = (bm + 1) * 128;
    for (int k0 = 0; k0 < kmax; k0 += 16) {
#pragma unroll
        for (int i = 0; i < 2; i++) {
            int row = lrA + i * 64;
            float4 v = *(const float4*)(Ar + (size_t)(bm * 128 + row) * SQ + k0 + lcA);
            As[lcA][row] = v.x; As[lcA+1][row] = v.y; As[lcA+2][row] = v.z; As[lcA+3][row] = v.w;
        }
        *(float4*)&Bs[lrB][lcB] = *(const float4*)(V + (size_t)(k0 + lrB) * DH + lcB);
        __syncthreads();
#pragma unroll
        for (int k = 0; k < 16; k++) {
            float a[8], bb[4];
#pragma unroll
            for (int i = 0; i < 8; i++) a[i] = As[k][ty * 8 + i];
#pragma unroll
            for (int j = 0; j < 4; j++) bb[j] = Bs[k][tx * 4 + j];
#pragma unroll
            for (int i = 0; i < 8; i++)
#pragma unroll
                for (int j = 0; j < 4; j++)
                    acc[i][j] = fmaf(a[i], bb[j], acc[i][j]);
        }
        __syncthreads();
    }

#pragma unroll
    for (int i = 0; i < 8; i++) {
        int qrow = bm * 128 + ty * 8 + i;
        float4 v = make_float4(acc[i][0], acc[i][1], acc[i][2], acc[i][3]);
        *(float4*)(g_ctx + ((size_t)(b * SQ + qrow)) * EMB + h * DH + tx * 4) = v;
    }
}

// ---------------------------------------------------------------------------
extern "C" void kernel_launch(void* const* d_in, const int* in_sizes, int n_in,
                              void* d_out, int out_size)
{
    const float* query = (const float*)d_in[0];
    const float* key_  = (const float*)d_in[1];
    const float* value = (const float*)d_in[2];
    const float* Wq = (const float*)d_in[3];
    const float* bq = (const float*)d_in[4];
    const float* Wk = (const float*)d_in[5];
    const float* bk = (const float*)d_in[6];
    const float* Wv = (const float*)d_in[7];
    const float* bv = (const float*)d_in[8];
    const float* Wo = (const float*)d_in[9];
    const float* bo = (const float*)d_in[10];

    const long long OUT_E = (long long)BSZ * SQ * EMB;  // 4,194,304
    const long long ATT_E = (long long)BH * SQ * SQ;    // 134,217,728

    float* outp = (float*)d_out;
    float* attn;
    if ((long long)out_size >= OUT_E + ATT_E) {
        attn = outp + OUT_E;  // tuple output: (out, attn) concatenated
    } else {
        void* p = nullptr;
        cudaGetSymbolAddress(&p, g_attn_fb);
        attn = (float*)p;
    }

    cudaFuncSetAttribute(scores_mma, cudaFuncAttributeMaxDynamicSharedMemorySize, SC_SMEM);

    dim3 gproj(EMB / 128, (BSZ * SQ) / 128);   // (8, 32)
    gemm_mma<1><<<gproj, 256>>>(query, Wq, bq, nullptr);
    gemm_mma<2><<<gproj, 256>>>(key_,  Wk, bk, nullptr);
    gemm_mma<3><<<gproj, 256>>>(value, Wv, bv, nullptr);

    dim3 gsc(SQ / 128, SQ / 128, BH);          // (16, 16, 32)
    scores_mma<<<gsc, 256, SC_SMEM>>>(attn);

    softmax_kernel<<<BH * SQ, 256>>>(attn);

    dim3 gpv(1, SQ / 128, BH);                 // (1, 16, 32)
    pv_kernel<<<gpv, 256>>>(attn);

    gemm_mma<0><<<gproj, 256>>>(nullptr, Wo, bo, outp);
}

// round 4
// speedup vs baseline: 3.2563x; 1.4096x over previous
#include <cuda_runtime.h>
#include <math.h>
#include <stdint.h>

// Problem constants
#define BSZ 2
#define HN  16
#define SQ  2048
#define DH  64
#define EMB 1024
#define BH  (BSZ*HN)

// Scratch (device globals; no allocations allowed)
__device__ float g_Qh[(size_t)BH * SQ * DH];      // [B,H,S,D]
__device__ float g_Kh[(size_t)BH * SQ * DH];
__device__ float g_Vh[(size_t)BH * SQ * DH];
__device__ float g_ctx[(size_t)BSZ * SQ * EMB];   // [B,S,E]
__device__ float g_attn_fb[(size_t)BH * SQ * SQ]; // fallback if attn not in d_out

// ===========================================================================
// mma.sync tf32 helpers (sm_80+ baseline PTX; no 'a'-gated features)
// ===========================================================================
__device__ __forceinline__ uint32_t f2tf(float x) {
    uint32_t r;
    asm("cvt.rna.tf32.f32 %0, %1;" : "=r"(r) : "f"(x));
    return r;
}

// D = A(16x8 tf32 row) * B(8x8 tf32 col) + D, fp32 accum
#define MMA_TF32(c, A0, A1, A2, A3, B0, B1)                                      \
    asm volatile("mma.sync.aligned.m16n8k8.row.col.f32.tf32.tf32.f32 "           \
                 "{%0,%1,%2,%3},{%4,%5,%6,%7},{%8,%9},{%0,%1,%2,%3};"            \
                 : "+f"((c)[0]), "+f"((c)[1]), "+f"((c)[2]), "+f"((c)[3])        \
                 : "r"(A0), "r"(A1), "r"(A2), "r"(A3), "r"(B0), "r"(B1))

// ===========================================================================
// TN GEMM via mma.sync tf32: C[m,n] = sum_k A[m,k]*W[n,k] + bias[n]
// 128x128 tile, BK=32, 256 threads (8 warps, each 32m x 64n).
// MODE 0: A := g_ctx, C[m*EMB+n]. MODE 1/2/3: scatter to g_Qh/g_Kh/g_Vh.
// ===========================================================================
template<int MODE>
__global__ void __launch_bounds__(256, 2) gemm_mma(const float* __restrict__ A,
                                                   const float* __restrict__ W,
                                                   const float* __restrict__ bias,
                                                   float* __restrict__ C)
{
    constexpr int K = EMB;        // 1024
    constexpr int LD = 36;        // row stride: %32==4 -> conflict-free frags

    __shared__ uint32_t As[128 * LD];
    __shared__ uint32_t Bs[128 * LD];

    const int tid  = threadIdx.x;
    const int wid  = tid >> 5, lane = tid & 31;
    const int g    = lane >> 2, t = lane & 3;
    const int wm   = (wid & 3) * 32;
    const int wn   = (wid >> 2) * 64;
    const int m0   = blockIdx.y * 128, n0 = blockIdx.x * 128;

    const float* __restrict__ Ap = (MODE == 0) ? g_ctx : A;

    const int lrow = tid >> 3;
    const int lc4  = tid & 7;
    const float* pA = Ap + (size_t)(m0 + lrow) * K + lc4 * 4;
    const float* pB = W  + (size_t)(n0 + lrow) * K + lc4 * 4;

    float acc[2][8][4];
#pragma unroll
    for (int i = 0; i < 2; i++)
#pragma unroll
        for (int j = 0; j < 8; j++)
#pragma unroll
            for (int l = 0; l < 4; l++) acc[i][j][l] = 0.f;

    float4 ra[4], rb[4];
#pragma unroll
    for (int i = 0; i < 4; i++) {
        ra[i] = *(const float4*)(pA + (size_t)(32 * i) * K);
        rb[i] = *(const float4*)(pB + (size_t)(32 * i) * K);
    }

    for (int kb = 0; kb < K / 32; kb++) {
#pragma unroll
        for (int i = 0; i < 4; i++) {
            uint32_t* da = &As[(lrow + 32 * i) * LD + lc4 * 4];
            da[0] = f2tf(ra[i].x); da[1] = f2tf(ra[i].y);
            da[2] = f2tf(ra[i].z); da[3] = f2tf(ra[i].w);
            uint32_t* db = &Bs[(lrow + 32 * i) * LD + lc4 * 4];
            db[0] = f2tf(rb[i].x); db[1] = f2tf(rb[i].y);
            db[2] = f2tf(rb[i].z); db[3] = f2tf(rb[i].w);
        }
        __syncthreads();

        if (kb + 1 < K / 32) {
#pragma unroll
            for (int i = 0; i < 4; i++) {
                ra[i] = *(const float4*)(pA + (size_t)(32 * i) * K + (kb + 1) * 32);
                rb[i] = *(const float4*)(pB + (size_t)(32 * i) * K + (kb + 1) * 32);
            }
        }

#pragma unroll
        for (int kt = 0; kt < 4; kt++) {
            const int k = kt * 8;
            uint32_t af[2][4];
#pragma unroll
            for (int mt = 0; mt < 2; mt++) {
                const int r = wm + mt * 16 + g;
                af[mt][0] = As[r * LD + k + t];
                af[mt][1] = As[(r + 8) * LD + k + t];
                af[mt][2] = As[r * LD + k + t + 4];
                af[mt][3] = As[(r + 8) * LD + k + t + 4];
            }
#pragma unroll
            for (int nt = 0; nt < 8; nt++) {
                const int n = wn + nt * 8 + g;
                const uint32_t b0 = Bs[n * LD + k + t];
                const uint32_t b1 = Bs[n * LD + k + t + 4];
#pragma unroll
                for (int mt = 0; mt < 2; mt++)
                    MMA_TF32(acc[mt][nt], af[mt][0], af[mt][1], af[mt][2], af[mt][3], b0, b1);
            }
        }
        __syncthreads();
    }

#pragma unroll
    for (int nt = 0; nt < 8; nt++) {
        const int n = n0 + wn + nt * 8 + 2 * t;
        const float b0 = bias[n], b1 = bias[n + 1];
#pragma unroll
        for (int mt = 0; mt < 2; mt++) {
            const int mlo = m0 + wm + mt * 16 + g;
            const int mhi = mlo + 8;
            float2 vlo = make_float2(acc[mt][nt][0] + b0, acc[mt][nt][1] + b1);
            float2 vhi = make_float2(acc[mt][nt][2] + b0, acc[mt][nt][3] + b1);
            if (MODE == 0) {
                *(float2*)(C + (size_t)mlo * EMB + n) = vlo;
                *(float2*)(C + (size_t)mhi * EMB + n) = vhi;
            } else {
                const int h = n >> 6, dd = n & 63;
                float* dst = (MODE == 1) ? g_Qh : (MODE == 2 ? g_Kh : g_Vh);
                const int blo = mlo / SQ, slo = mlo % SQ;
                const int bhi = mhi / SQ, shi = mhi % SQ;
                *(float2*)(dst + ((size_t)(blo * HN + h) * SQ + slo) * DH + dd) = vlo;
                *(float2*)(dst + ((size_t)(bhi * HN + h) * SQ + shi) * DH + dd) = vhi;
            }
        }
    }
}

// ---------------------------------------------------------------------------
// Causal scores via mma.sync tf32: attn[bh,q,k] = 0.125*dot(Q[q],K[k]), k<=q
// ---------------------------------------------------------------------------
#define SC_LD 68
#define SC_SMEM (2 * 128 * SC_LD * 4)

__global__ void __launch_bounds__(256) scores_mma(float* __restrict__ attn)
{
    const int bh = blockIdx.z;
    const int bm = blockIdx.y, bn = blockIdx.x;
    float* out = attn + (size_t)bh * SQ * SQ;
    const int tid = threadIdx.x;

    if (bn > bm) { // fully masked tile -> exact zeros
#pragma unroll
        for (int it = 0; it < 16; it++) {
            int idx = it * 256 + tid;
            int r = idx >> 5;
            int c = idx & 31;
            *(float4*)(out + (size_t)(bm * 128 + r) * SQ + bn * 128 + c * 4) =
                make_float4(0.f, 0.f, 0.f, 0.f);
        }
        return;
    }

    extern __shared__ uint32_t sc_smem[];
    uint32_t* Qs = sc_smem;
    uint32_t* Ks = sc_smem + 128 * SC_LD;

    const float* Q  = g_Qh + (size_t)bh * SQ * DH;
    const float* Kp = g_Kh + (size_t)bh * SQ * DH;

    const int lrow = tid >> 4;
    const int lq4  = tid & 15;
#pragma unroll
    for (int i = 0; i < 8; i++) {
        const int r = lrow + 16 * i;
        float4 vq = *(const float4*)(Q  + (size_t)(bm * 128 + r) * DH + lq4 * 4);
        float4 vk = *(const float4*)(Kp + (size_t)(bn * 128 + r) * DH + lq4 * 4);
        uint32_t* dq = &Qs[r * SC_LD + lq4 * 4];
        dq[0] = f2tf(vq.x); dq[1] = f2tf(vq.y); dq[2] = f2tf(vq.z); dq[3] = f2tf(vq.w);
        uint32_t* dk = &Ks[r * SC_LD + lq4 * 4];
        dk[0] = f2tf(vk.x); dk[1] = f2tf(vk.y); dk[2] = f2tf(vk.z); dk[3] = f2tf(vk.w);
    }
    __syncthreads();

    const int wid = tid >> 5, lane = tid & 31;
    const int g = lane >> 2, t = lane & 3;
    const int wm = (wid & 3) * 32;
    const int wn = (wid >> 2) * 64;

    float acc[2][8][4];
#pragma unroll
    for (int i = 0; i < 2; i++)
#pragma unroll
        for (int j = 0; j < 8; j++)
#pragma unroll
            for (int l = 0; l < 4; l++) acc[i][j][l] = 0.f;

#pragma unroll
    for (int kt = 0; kt < 8; kt++) {
        const int k = kt * 8;
        uint32_t af[2][4];
#pragma unroll
        for (int mt = 0; mt < 2; mt++) {
            const int r = wm + mt * 16 + g;
            af[mt][0] = Qs[r * SC_LD + k + t];
            af[mt][1] = Qs[(r + 8) * SC_LD + k + t];
            af[mt][2] = Qs[r * SC_LD + k + t + 4];
            af[mt][3] = Qs[(r + 8) * SC_LD + k + t + 4];
        }
#pragma unroll
        for (int nt = 0; nt < 8; nt++) {
            const int n = wn + nt * 8 + g;
            const uint32_t b0 = Ks[n * SC_LD + k + t];
            const uint32_t b1 = Ks[n * SC_LD + k + t + 4];
#pragma unroll
            for (int mt = 0; mt < 2; mt++)
                MMA_TF32(acc[mt][nt], af[mt][0], af[mt][1], af[mt][2], af[mt][3], b0, b1);
        }
    }

    const float scale = 0.125f;
#pragma unroll
    for (int nt = 0; nt < 8; nt++) {
        const int c = bn * 128 + wn + nt * 8 + 2 * t;
#pragma unroll
        for (int mt = 0; mt < 2; mt++) {
            const int rlo = bm * 128 + wm + mt * 16 + g;
            const int rhi = rlo + 8;
            float2 vlo = make_float2(c <= rlo ? acc[mt][nt][0] * scale : 0.f,
                                     c + 1 <= rlo ? acc[mt][nt][1] * scale : 0.f);
            float2 vhi = make_float2(c <= rhi ? acc[mt][nt][2] * scale : 0.f,
                                     c + 1 <= rhi ? acc[mt][nt][3] * scale : 0.f);
            *(float2*)(out + (size_t)rlo * SQ + c) = vlo;
            *(float2*)(out + (size_t)rhi * SQ + c) = vhi;
        }
    }
}

// ---------------------------------------------------------------------------
// Single-pass register-resident causal row softmax. One 256-thread CTA per
// row: whole 2048-float row lives in 8 regs/thread. 1 DRAM read + 1 write.
// ---------------------------------------------------------------------------
__global__ void __launch_bounds__(256) softmax_reg(float* __restrict__ attn)
{
    const size_t rid = blockIdx.x;
    const int q = (int)(rid & (SQ - 1));
    const int L = q + 1;
    float* row = attn + rid * SQ;
    const int tid = threadIdx.x;
    __shared__ float sred[8];

    // load: 2 float4 per thread (indices tid and tid+256 in float4 units)
    float4 v0 = *(const float4*)(row + tid * 4);
    float4 v1 = *(const float4*)(row + (tid + 256) * 4);
    const int j0 = tid * 4, j1 = (tid + 256) * 4;

    // row max over live elements
    float m = -INFINITY;
    if (j0 + 0 < L) m = fmaxf(m, v0.x);
    if (j0 + 1 < L) m = fmaxf(m, v0.y);
    if (j0 + 2 < L) m = fmaxf(m, v0.z);
    if (j0 + 3 < L) m = fmaxf(m, v0.w);
    if (j1 + 0 < L) m = fmaxf(m, v1.x);
    if (j1 + 1 < L) m = fmaxf(m, v1.y);
    if (j1 + 2 < L) m = fmaxf(m, v1.z);
    if (j1 + 3 < L) m = fmaxf(m, v1.w);
#pragma unroll
    for (int o = 16; o; o >>= 1) m = fmaxf(m, __shfl_xor_sync(0xffffffffu, m, o));
    if ((tid & 31) == 0) sred[tid >> 5] = m;
    __syncthreads();
    if (tid < 32) {
        float x = (tid < 8) ? sred[tid] : -INFINITY;
#pragma unroll
        for (int o = 4; o; o >>= 1) x = fmaxf(x, __shfl_xor_sync(0xffffffffu, x, o));
        if (tid == 0) sred[0] = x;
    }
    __syncthreads();
    m = sred[0];
    __syncthreads();

    // exp + masked sum
    float4 e0, e1;
    e0.x = __expf(v0.x - m); e0.y = __expf(v0.y - m);
    e0.z = __expf(v0.z - m); e0.w = __expf(v0.w - m);
    e1.x = __expf(v1.x - m); e1.y = __expf(v1.y - m);
    e1.z = __expf(v1.z - m); e1.w = __expf(v1.w - m);

    float s = 0.f;
    if (j0 + 0 < L) s += e0.x;
    if (j0 + 1 < L) s += e0.y;
    if (j0 + 2 < L) s += e0.z;
    if (j0 + 3 < L) s += e0.w;
    if (j1 + 0 < L) s += e1.x;
    if (j1 + 1 < L) s += e1.y;
    if (j1 + 2 < L) s += e1.z;
    if (j1 + 3 < L) s += e1.w;
#pragma unroll
    for (int o = 16; o; o >>= 1) s += __shfl_xor_sync(0xffffffffu, s, o);
    if ((tid & 31) == 0) sred[tid >> 5] = s;
    __syncthreads();
    if (tid < 32) {
        float x = (tid < 8) ? sred[tid] : 0.f;
#pragma unroll
        for (int o = 4; o; o >>= 1) x += __shfl_xor_sync(0xffffffffu, x, o);
        if (tid == 0) sred[0] = x;
    }
    __syncthreads();
    const float inv = 1.f / sred[0];

    // masked store (tail beyond L must stay exact zero)
    e0.x *= inv; e0.y *= inv; e0.z *= inv; e0.w *= inv;
    e1.x *= inv; e1.y *= inv; e1.z *= inv; e1.w *= inv;
    if (j0 + 3 < L) {
        *(float4*)(row + j0) = e0;
    } else {
        if (j0 + 0 < L) row[j0 + 0] = e0.x;
        if (j0 + 1 < L) row[j0 + 1] = e0.y;
        if (j0 + 2 < L) row[j0 + 2] = e0.z;
        if (j0 + 3 < L) row[j0 + 3] = e0.w;
    }
    if (j1 + 3 < L) {
        *(float4*)(row + j1) = e1;
    } else {
        if (j1 + 0 < L) row[j1 + 0] = e1.x;
        if (j1 + 1 < L) row[j1 + 1] = e1.y;
        if (j1 + 2 < L) row[j1 + 2] = e1.z;
        if (j1 + 3 < L) row[j1 + 3] = e1.w;
    }
}

// ---------------------------------------------------------------------------
// PV via mma.sync tf32: ctx[b,q,h*64+d] = sum_k attn[bh,q,k] * V[bh,k,d]
// 128q x 64d tile per CTA; K loop truncated causally. Above-diagonal attn
// entries are exact zeros in gmem, so no masking needed.
// 8 warps, each 16q x 64d. BK=32.
// ---------------------------------------------------------------------------
#define PV_LDA 36   // P tile row stride (words)
#define PV_LDB 72   // V tile row stride: %32==8 -> B-frag conflict-free

__global__ void __launch_bounds__(256, 2) pv_mma(const float* __restrict__ attn)
{
    const int bh = blockIdx.z;
    const int b = bh >> 4, h = bh & 15;
    const int bm = (int)gridDim.y - 1 - (int)blockIdx.y;  // long tiles first
    const float* Ar = attn + (size_t)bh * SQ * SQ + (size_t)bm * 128 * SQ;
    const float* V  = g_Vh + (size_t)bh * SQ * DH;

    __shared__ uint32_t Ps[128 * PV_LDA];
    __shared__ uint32_t Vs[32 * PV_LDB];

    const int tid = threadIdx.x;
    const int wid = tid >> 5, lane = tid & 31;
    const int g = lane >> 2, t = lane & 3;
    const int wm = wid * 16;

    // loaders
    const int prow = tid >> 3, pc4 = tid & 7;       // P: 128x32, 4 float4/thr
    const int vrow = tid >> 4, vc4 = tid & 15;      // V: 32x64,  2 float4/thr

    float acc[8][4];
#pragma unroll
    for (int j = 0; j < 8; j++)
#pragma unroll
        for (int l = 0; l < 4; l++) acc[j][l] = 0.f;

    const int nkb = (bm + 1) * 4;  // 32-wide k blocks

    float4 rp[4], rv[2];
#pragma unroll
    for (int i = 0; i < 4; i++)
        rp[i] = *(const float4*)(Ar + (size_t)(prow + 32 * i) * SQ + pc4 * 4);
#pragma unroll
    for (int i = 0; i < 2; i++)
        rv[i] = *(const float4*)(V + (size_t)(vrow + 16 * i) * DH + vc4 * 4);

    for (int kb = 0; kb < nkb; kb++) {
#pragma unroll
        for (int i = 0; i < 4; i++) {
            uint32_t* dp = &Ps[(prow + 32 * i) * PV_LDA + pc4 * 4];
            dp[0] = f2tf(rp[i].x); dp[1] = f2tf(rp[i].y);
            dp[2] = f2tf(rp[i].z); dp[3] = f2tf(rp[i].w);
        }
#pragma unroll
        for (int i = 0; i < 2; i++) {
            uint32_t* dv = &Vs[(vrow + 16 * i) * PV_LDB + vc4 * 4];
            dv[0] = f2tf(rv[i].x); dv[1] = f2tf(rv[i].y);
            dv[2] = f2tf(rv[i].z); dv[3] = f2tf(rv[i].w);
        }
        __syncthreads();

        if (kb + 1 < nkb) {
#pragma unroll
            for (int i = 0; i < 4; i++)
                rp[i] = *(const float4*)(Ar + (size_t)(prow + 32 * i) * SQ
                                            + (kb + 1) * 32 + pc4 * 4);
#pragma unroll
            for (int i = 0; i < 2; i++)
                rv[i] = *(const float4*)(V + (size_t)((kb + 1) * 32 + vrow + 16 * i) * DH
                                           + vc4 * 4);
        }

#pragma unroll
        for (int kt = 0; kt < 4; kt++) {
            const int k = kt * 8;
            uint32_t a0 = Ps[(wm + g) * PV_LDA + k + t];
            uint32_t a1 = Ps[(wm + g + 8) * PV_LDA + k + t];
            uint32_t a2 = Ps[(wm + g) * PV_LDA + k + t + 4];
            uint32_t a3 = Ps[(wm + g + 8) * PV_LDA + k + t + 4];
#pragma unroll
            for (int nt = 0; nt < 8; nt++) {
                const uint32_t b0 = Vs[(k + t) * PV_LDB + nt * 8 + g];
                const uint32_t b1 = Vs[(k + t + 4) * PV_LDB + nt * 8 + g];
                MMA_TF32(acc[nt], a0, a1, a2, a3, b0, b1);
            }
        }
        __syncthreads();
    }

    // epilogue: rows bm*128+wm+g and +8; cols nt*8+2t
    const int rlo = bm * 128 + wm + g;
    const int rhi = rlo + 8;
    float* olo = g_ctx + ((size_t)(b * SQ + rlo)) * EMB + h * DH;
    float* ohi = g_ctx + ((size_t)(b * SQ + rhi)) * EMB + h * DH;
#pragma unroll
    for (int nt = 0; nt < 8; nt++) {
        const int c = nt * 8 + 2 * t;
        *(float2*)(olo + c) = make_float2(acc[nt][0], acc[nt][1]);
        *(float2*)(ohi + c) = make_float2(acc[nt][2], acc[nt][3]);
    }
}

// ---------------------------------------------------------------------------
extern "C" void kernel_launch(void* const* d_in, const int* in_sizes, int n_in,
                              void* d_out, int out_size)
{
    const float* query = (const float*)d_in[0];
    const float* key_  = (const float*)d_in[1];
    const float* value = (const float*)d_in[2];
    const float* Wq = (const float*)d_in[3];
    const float* bq = (const float*)d_in[4];
    const float* Wk = (const float*)d_in[5];
    const float* bk = (const float*)d_in[6];
    const float* Wv = (const float*)d_in[7];
    const float* bv = (const float*)d_in[8];
    const float* Wo = (const float*)d_in[9];
    const float* bo = (const float*)d_in[10];

    const long long OUT_E = (long long)BSZ * SQ * EMB;  // 4,194,304
    const long long ATT_E = (long long)BH * SQ * SQ;    // 134,217,728

    float* outp = (float*)d_out;
    float* attn;
    if ((long long)out_size >= OUT_E + ATT_E) {
        attn = outp + OUT_E;  // tuple output: (out, attn) concatenated
    } else {
        void* p = nullptr;
        cudaGetSymbolAddress(&p, g_attn_fb);
        attn = (float*)p;
    }

    cudaFuncSetAttribute(scores_mma, cudaFuncAttributeMaxDynamicSharedMemorySize, SC_SMEM);

    dim3 gproj(EMB / 128, (BSZ * SQ) / 128);   // (8, 32)
    gemm_mma<1><<<gproj, 256>>>(query, Wq, bq, nullptr);
    gemm_mma<2><<<gproj, 256>>>(key_,  Wk, bk, nullptr);
    gemm_mma<3><<<gproj, 256>>>(value, Wv, bv, nullptr);

    dim3 gsc(SQ / 128, SQ / 128, BH);          // (16, 16, 32)
    scores_mma<<<gsc, 256, SC_SMEM>>>(attn);

    softmax_reg<<<BH * SQ, 256>>>(attn);

    dim3 gpv(1, SQ / 128, BH);                 // (1, 16, 32)
    pv_mma<<<gpv, 256>>>(attn);

    gemm_mma<0><<<gproj, 256>>>(nullptr, Wo, bo, outp);
}